// round 15
// baseline (speedup 1.0000x reference)
#include <cuda_runtime.h>
#include <math.h>

#define BATCH 64
#define SEQ   200
#define EMBED 64
#define NCAPS 50
#define R_TOT 3072
#define LOUT  96
#define RT    32
#define NRB   96
#define WS    132
#define US2   260
#define NPAD  19008

typedef unsigned long long ull_t;

__device__ __align__(16) float g_cwt[576 * 256];
__device__ __align__(16) float g_u[(size_t)BATCH * R_TOT * 8];
__device__ __align__(16) float g_blog[(size_t)NCAPS * R_TOT * BATCH];
__device__ __align__(16) float g_m[R_TOT * BATCH];
__device__ __align__(16) float g_invZ[R_TOT * BATCH];
__device__ __align__(16) float g_spart[(size_t)NCAPS * NRB * BATCH * 16];
__device__ __align__(16) float g_v[BATCH * NCAPS * 16];
__device__ __align__(16) float g_h1[BATCH * 512];
__device__ __align__(16) float g_h2[BATCH * 1024];
__device__ __align__(16) float g_r3p[2 * BATCH * NPAD];

__device__ __forceinline__ ull_t pk2(float a, float b) {
    ull_t r;
    asm("mov.b64 %0, {%1, %2};" : "=l"(r) : "f"(a), "f"(b));
    return r;
}
__device__ __forceinline__ void fma2(ull_t& d, ull_t a, ull_t b) {
    asm("fma.rn.f32x2 %0, %1, %2, %0;" : "+l"(d) : "l"(a), "l"(b));
}
__device__ __forceinline__ ull_t add2(ull_t a, ull_t b) {
    ull_t r;
    asm("add.rn.f32x2 %0, %1, %2;" : "=l"(r) : "l"(a), "l"(b));
    return r;
}
__device__ __forceinline__ float2 upk(ull_t v) {
    float2 f;
    asm("mov.b64 {%0, %1}, %2;" : "=f"(f.x), "=f"(f.y) : "l"(v));
    return f;
}
__device__ __forceinline__ void cpa16(void* s, const void* g) {
    unsigned sa = (unsigned)__cvta_generic_to_shared(s);
    asm volatile("cp.async.ca.shared.global [%0], [%1], 16;" :: "r"(sa), "l"(g));
}
#define CP_COMMIT asm volatile("cp.async.commit_group;")
#define CP_WAIT0  asm volatile("cp.async.wait_group 0;" ::: "memory")

__device__ __forceinline__ void stage_W(const float* __restrict__ W, int c, int r0,
                                        int tid, float* dst) {
#pragma unroll
    for (int k = 0; k < 4; k++) {
        int idx = tid + k * 256;
        int rl = idx >> 5, q = idx & 31;
        cpa16(dst + rl * WS + q * 4, W + ((size_t)c * R_TOT + r0 + rl) * 128 + q * 4);
    }
}
// stage u half-tile: 32 routes x 32 batches x 8
__device__ __forceinline__ void stage_u32(int r0, int bbase, int tid, float* dst) {
#pragma unroll
    for (int k = 0; k < 8; k++) {
        int idx = tid + k * 256;
        int b = idx >> 6, t = idx & 63;
        int rl = t >> 1, i4 = (t & 1) * 4;
        cpa16(dst + rl * US2 + b * 8 + i4,
              g_u + ((size_t)(bbase + b) * R_TOT + r0 + rl) * 8 + i4);
    }
}

__global__ void k_transpose_w(const float* __restrict__ conv_w) {
    g_cwt[blockIdx.x * 256 + threadIdx.x] = conv_w[threadIdx.x * 576 + blockIdx.x];
}

__global__ void k_conv(const int* __restrict__ x, const float* __restrict__ emb,
                       const float* __restrict__ conv_b) {
    int b = blockIdx.x, l0 = blockIdx.y * 16, tid = threadIdx.x;
    __shared__ float xs[39 * 64];
    for (int idx = tid; idx < 39 * 16; idx += 256) {
        int row = idx >> 4, col = idx & 15;
        int tok = x[b * SEQ + 2 * l0 + row];
        ((float4*)xs)[row * 16 + col] = ((const float4*)(emb + (size_t)tok * EMBED))[col];
    }
    __syncthreads();
    int ch = tid;
    float acc[16], bias = conv_b[ch];
#pragma unroll
    for (int j = 0; j < 16; j++) acc[j] = bias;
    for (int e = 0; e < 64; e++) {
#pragma unroll
        for (int k = 0; k < 9; k++) {
            float w = g_cwt[(e * 9 + k) * 256 + ch];
#pragma unroll
            for (int j = 0; j < 16; j++)
                acc[j] = fmaf(xs[(2 * j + k) * 64 + e], w, acc[j]);
        }
    }
    int g = ch >> 3, i = ch & 7;
#pragma unroll
    for (int j = 0; j < 16; j++) {
        float val = acc[j] > 0.f ? acc[j] : 0.f;
        g_u[((size_t)b * R_TOT + g * LOUT + l0 + j) * 8 + i] = val;
    }
}

// ---------------- pass_s: 256 thr, 4 routes x 1 batch, batch-split ----------
// grid (96 rb, 25 cp, 2 bh). rg = tid&7, bg = tid>>3 (32 batches of half).
template <int MODE>
__global__ void __launch_bounds__(256, 3) k_pass_s(const float* __restrict__ W) {
    __shared__ float u_sh[RT * US2];
    __shared__ float Ws[2][RT * WS];
    int rb = blockIdx.x, c0 = blockIdx.y * 2, bbase = blockIdx.z * 32;
    int r0 = rb * RT, tid = threadIdx.x;
    int rg = tid & 7, bg = tid >> 3;
    int b = bbase + bg;

    float mr[4], izr[4];
    if (MODE == 1) {
#pragma unroll
        for (int rr = 0; rr < 4; rr++) {
            int r = r0 + rr * 8 + rg;
            mr[rr]  = g_m[r * 64 + b];
            izr[rr] = g_invZ[r * 64 + b];
        }
    }
    stage_u32(r0, bbase, tid, u_sh);
    stage_W(W, c0, r0, tid, Ws[0]);
    CP_COMMIT; CP_WAIT0; __syncthreads();

#pragma unroll
    for (int cc = 0; cc < 2; cc++) {
        int c = c0 + cc;
        if (cc == 0) { stage_W(W, c0 + 1, r0, tid, Ws[1]); CP_COMMIT; }

        float cf[4];
        if (MODE == 1) {
#pragma unroll
            for (int rr = 0; rr < 4; rr++) {
                float bl = g_blog[((size_t)c * R_TOT + r0 + rr * 8 + rg) * 64 + b];
                cf[rr] = __expf(bl - mr[rr]) * izr[rr];
            }
        }

        ull_t acc[8];
#pragma unroll
        for (int k = 0; k < 8; k++) acc[k] = 0ull;

#pragma unroll
        for (int rr = 0; rr < 4; rr++) {
            int rl = rr * 8 + rg;
            const float* up = &u_sh[rl * US2 + bg * 8];
            float4 x0 = *(const float4*)(up);
            float4 x1 = *(const float4*)(up + 4);
            float cfj = (MODE == 0) ? 0.02f : cf[rr];
            float su[8] = {cfj*x0.x, cfj*x0.y, cfj*x0.z, cfj*x0.w,
                           cfj*x1.x, cfj*x1.y, cfj*x1.z, cfj*x1.w};
            const float* wrow = &Ws[cc][rl * WS];
#pragma unroll
            for (int i = 0; i < 8; i++) {
                ull_t s = pk2(su[i], su[i]);
#pragma unroll
                for (int o4 = 0; o4 < 4; o4++) {
                    ulonglong2 wp = *(const ulonglong2*)&wrow[i * 16 + o4 * 4];
                    fma2(acc[o4 * 2 + 0], s, wp.x);
                    fma2(acc[o4 * 2 + 1], s, wp.y);
                }
            }
        }
#pragma unroll
        for (int m = 1; m <= 4; m <<= 1)
#pragma unroll
            for (int k = 0; k < 8; k++)
                acc[k] = add2(acc[k], __shfl_xor_sync(0xffffffffu, acc[k], m));
        if (rg == 0) {
            ull_t* dst = (ull_t*)(g_spart + (((size_t)c * NRB + rb) * BATCH + b) * 16);
#pragma unroll
            for (int k = 0; k < 8; k++) dst[k] = acc[k];
        }
        if (cc == 0) { CP_WAIT0; __syncthreads(); }
    }
}

// ---------------- pass_agree: batch-split ------------------------------------
template <int ACC>
__global__ void __launch_bounds__(256, 3) k_pass_agree(const float* __restrict__ W) {
    __shared__ float u_sh[RT * US2];
    __shared__ float Ws[2][RT * WS];
    int rb = blockIdx.x, c0 = blockIdx.y * 2, bbase = blockIdx.z * 32;
    int r0 = rb * RT, tid = threadIdx.x;
    int rg = tid & 7, bg = tid >> 3;
    int b = bbase + bg;

    stage_u32(r0, bbase, tid, u_sh);
    stage_W(W, c0, r0, tid, Ws[0]);
    CP_COMMIT; CP_WAIT0; __syncthreads();

#pragma unroll
    for (int cc = 0; cc < 2; cc++) {
        int c = c0 + cc;
        if (cc == 0) { stage_W(W, c0 + 1, r0, tid, Ws[1]); CP_COMMIT; }

        ull_t vp[8];
        {
            const ulonglong2* vsrc =
                (const ulonglong2*)(g_v + ((size_t)b * NCAPS + c) * 16);
#pragma unroll
            for (int q = 0; q < 4; q++) {
                ulonglong2 t = vsrc[q];
                vp[q * 2] = t.x; vp[q * 2 + 1] = t.y;
            }
        }
#pragma unroll
        for (int rr = 0; rr < 4; rr++) {
            int rl = rr * 8 + rg;
            int r = r0 + rl;
            const float* wrow = &Ws[cc][rl * WS];
            float gg[8];
#pragma unroll
            for (int i = 0; i < 8; i++) {
                ull_t gi = 0ull;
#pragma unroll
                for (int o4 = 0; o4 < 4; o4++) {
                    ulonglong2 wp = *(const ulonglong2*)&wrow[i * 16 + o4 * 4];
                    fma2(gi, wp.x, vp[o4 * 2]);
                    fma2(gi, wp.y, vp[o4 * 2 + 1]);
                }
                float2 t = upk(gi);
                gg[i] = t.x + t.y;
            }
            const float* up = &u_sh[rl * US2 + bg * 8];
            float4 x0 = *(const float4*)(up);
            float4 x1 = *(const float4*)(up + 4);
            float add = x0.x*gg[0] + x0.y*gg[1] + x0.z*gg[2] + x0.w*gg[3]
                      + x1.x*gg[4] + x1.y*gg[5] + x1.z*gg[6] + x1.w*gg[7];
            float* dst = g_blog + ((size_t)c * R_TOT + r) * 64 + b;
            if (ACC) add += *dst;
            *dst = add;
        }
        if (cc == 0) { CP_WAIT0; __syncthreads(); }
    }
}

__global__ void k_stats() {
    int idx = blockIdx.x * 256 + threadIdx.x;   // r*64+b
    float mx = -1e30f;
#pragma unroll
    for (int c = 0; c < NCAPS; c++)
        mx = fmaxf(mx, g_blog[(size_t)c * (R_TOT * 64) + idx]);
    float sum = 0.f;
#pragma unroll
    for (int c = 0; c < NCAPS; c++)
        sum += __expf(g_blog[(size_t)c * (R_TOT * 64) + idx] - mx);
    g_m[idx] = mx;
    g_invZ[idx] = 1.f / sum;
}

__global__ void k_finalize_v(float* __restrict__ out_len) {
    int gid = blockIdx.x * 256 + threadIdx.x;   // (b*50+c)*16+o, 51200
    int o = gid & 15;
    int bc = gid >> 4;
    int b = bc / NCAPS, c = bc % NCAPS;
    const float* base = g_spart + ((size_t)c * NRB * BATCH + b) * 16 + o;
    float s0 = 0.f, s1 = 0.f, s2 = 0.f, s3 = 0.f;
#pragma unroll 6
    for (int rb = 0; rb < NRB; rb += 4) {
        s0 += base[(size_t)(rb + 0) * BATCH * 16];
        s1 += base[(size_t)(rb + 1) * BATCH * 16];
        s2 += base[(size_t)(rb + 2) * BATCH * 16];
        s3 += base[(size_t)(rb + 3) * BATCH * 16];
    }
    float s = (s0 + s1) + (s2 + s3);
    float nsq = s * s;
#pragma unroll
    for (int m = 1; m <= 8; m <<= 1)
        nsq += __shfl_xor_sync(0xffffffffu, nsq, m);
    float norm = sqrtf(nsq);
    float f = nsq / (1.f + nsq) / (norm + 1e-8f);
    g_v[gid] = f * s;
    if (o == 0) out_len[bc] = f * norm;
}

__global__ void k_mlp1(const float* __restrict__ w1, const float* __restrict__ b1,
                       const float* __restrict__ len) {
    int b = blockIdx.x;
    __shared__ float vv[16];
    __shared__ int cb_sh;
    if (threadIdx.x < 32) {
        float best = -1.f; int bi = 0;
        for (int c = threadIdx.x; c < NCAPS; c += 32) {
            float L = len[b * NCAPS + c];
            if (L > best || (L == best && c < bi)) { best = L; bi = c; }
        }
#pragma unroll
        for (int mm = 16; mm >= 1; mm >>= 1) {
            float ob = __shfl_xor_sync(0xffffffffu, best, mm);
            int oi = __shfl_xor_sync(0xffffffffu, bi, mm);
            if (ob > best || (ob == best && oi < bi)) { best = ob; bi = oi; }
        }
        if (threadIdx.x == 0) cb_sh = bi;
    }
    __syncthreads();
    int cb = cb_sh;
    if (threadIdx.x < 16)
        vv[threadIdx.x] = g_v[((size_t)b * NCAPS + cb) * 16 + threadIdx.x];
    __syncthreads();
    int n = threadIdx.x;
    float acc = b1[n];
#pragma unroll
    for (int o = 0; o < 16; o++)
        acc = fmaf(vv[o], w1[(size_t)(cb * 16 + o) * 512 + n], acc);
    g_h1[b * 512 + n] = acc > 0.f ? acc : 0.f;
}

__global__ void k_mlp2(const float* __restrict__ w2, const float* __restrict__ b2) {
    int b = blockIdx.x;
    __shared__ float hh[512];
    for (int i = threadIdx.x; i < 512; i += 256) hh[i] = g_h1[b * 512 + i];
    __syncthreads();
    int n0 = threadIdx.x * 4;
    float4 acc = *(const float4*)(b2 + n0);
    for (int k = 0; k < 512; k++) {
        float h = hh[k];
        float4 w = *(const float4*)(w2 + (size_t)k * 1024 + n0);
        acc.x = fmaf(h, w.x, acc.x); acc.y = fmaf(h, w.y, acc.y);
        acc.z = fmaf(h, w.z, acc.z); acc.w = fmaf(h, w.w, acc.w);
    }
    acc.x = fmaxf(acc.x, 0.f); acc.y = fmaxf(acc.y, 0.f);
    acc.z = fmaxf(acc.z, 0.f); acc.w = fmaxf(acc.w, 0.f);
    *(float4*)(g_h2 + (size_t)b * 1024 + n0) = acc;
}

// ---------------- mlp3: split-K x2, partials to g_r3p -----------------------
__global__ void k_mlp3(const float* __restrict__ w3) {
    int ncol0 = blockIdx.x * 128;
    int kh = blockIdx.y;                 // 0/1 -> kc halves
    __shared__ ull_t h2p[32 * 33];
    __shared__ float w3s[32 * 128];
    int tid = threadIdx.x;
    int bt = tid >> 5, ntid = tid & 31;
    int bp0 = bt * 4, n_off = ntid * 4;
    ull_t acc2[4][4];
#pragma unroll
    for (int jp = 0; jp < 4; jp++)
#pragma unroll
        for (int e = 0; e < 4; e++) acc2[jp][e] = 0ull;
    for (int kc = kh * 16; kc < kh * 16 + 16; kc++) {
        for (int idx = tid; idx < 32 * 32; idx += 256) {
            int bp = idx >> 5, kk = idx & 31;
            h2p[bp * 33 + kk] = pk2(g_h2[(size_t)(2 * bp) * 1024 + kc * 32 + kk],
                                    g_h2[(size_t)(2 * bp + 1) * 1024 + kc * 32 + kk]);
        }
        for (int idx = tid; idx < 32 * 32; idx += 256) {
            int kk = idx >> 5, jj = idx & 31;
            int col = ncol0 + jj * 4;
            float4 val;
            const float* row = w3 + (size_t)(kc * 32 + kk) * 19000;
            if (col + 3 < 19000) val = *(const float4*)(row + col);
            else {
                val.x = (col + 0 < 19000) ? row[col + 0] : 0.f;
                val.y = (col + 1 < 19000) ? row[col + 1] : 0.f;
                val.z = (col + 2 < 19000) ? row[col + 2] : 0.f;
                val.w = (col + 3 < 19000) ? row[col + 3] : 0.f;
            }
            *(float4*)&w3s[kk * 128 + jj * 4] = val;
        }
        __syncthreads();
        for (int kk = 0; kk < 32; kk++) {
            float4 w = *(const float4*)&w3s[kk * 128 + n_off];
            ull_t wp0 = pk2(w.x, w.x), wp1 = pk2(w.y, w.y);
            ull_t wp2 = pk2(w.z, w.z), wp3 = pk2(w.w, w.w);
#pragma unroll
            for (int jp = 0; jp < 4; jp++) {
                ull_t h = h2p[(bp0 + jp) * 33 + kk];
                fma2(acc2[jp][0], h, wp0); fma2(acc2[jp][1], h, wp1);
                fma2(acc2[jp][2], h, wp2); fma2(acc2[jp][3], h, wp3);
            }
        }
        __syncthreads();
    }
    float* part = g_r3p + (size_t)kh * BATCH * NPAD;
    int n = ncol0 + n_off;
#pragma unroll
    for (int jp = 0; jp < 4; jp++) {
        int b_even = (bp0 + jp) * 2;
#pragma unroll
        for (int e = 0; e < 4; e++) {
            int nn = n + e;
            if (nn < 19000) {
                float2 t = upk(acc2[jp][e]);
                part[(size_t)b_even * NPAD + nn] = t.x;
                part[(size_t)(b_even + 1) * NPAD + nn] = t.y;
            }
        }
    }
}

__global__ void k_mlp3fin(const float* __restrict__ b3, float* __restrict__ out_recon) {
    int gid = blockIdx.x * 256 + threadIdx.x;     // 64 * 4750 n4-tiles
    if (gid >= BATCH * 4750) return;
    int b = gid / 4750;
    int n = (gid - b * 4750) * 4;
    float4 p0 = *(const float4*)(g_r3p + (size_t)b * NPAD + n);
    float4 p1 = *(const float4*)(g_r3p + (size_t)(BATCH * NPAD) + (size_t)b * NPAD + n);
    float4 bb = *(const float4*)(b3 + n);
    float4 r;
    r.x = 1.f / (1.f + __expf(-(p0.x + p1.x + bb.x)));
    r.y = 1.f / (1.f + __expf(-(p0.y + p1.y + bb.y)));
    r.z = 1.f / (1.f + __expf(-(p0.z + p1.z + bb.z)));
    r.w = 1.f / (1.f + __expf(-(p0.w + p1.w + bb.w)));
    *(float4*)(out_recon + (size_t)b * 19000 + n) = r;
}

extern "C" void kernel_launch(void* const* d_in, const int* in_sizes, int n_in,
                              void* d_out, int out_size) {
    const int*   x      = (const int*)d_in[0];
    const float* emb    = (const float*)d_in[1];
    const float* conv_w = (const float*)d_in[2];
    const float* conv_b = (const float*)d_in[3];
    const float* W      = (const float*)d_in[4];
    const float* w1     = (const float*)d_in[5];
    const float* b1     = (const float*)d_in[6];
    const float* w2     = (const float*)d_in[7];
    const float* b2     = (const float*)d_in[8];
    const float* w3     = (const float*)d_in[9];
    const float* b3     = (const float*)d_in[10];
    float* out       = (float*)d_out;
    float* out_len   = out;
    float* out_recon = out + BATCH * NCAPS;

    dim3 pg(NRB, NCAPS / 2, 2);   // 96 x 25 x 2 batch-halves

    k_transpose_w<<<576, 256>>>(conv_w);
    k_conv<<<dim3(64, 6), 256>>>(x, emb, conv_b);

    k_pass_s<0><<<pg, 256>>>(W);
    k_finalize_v<<<200, 256>>>(out_len);

    k_pass_agree<0><<<pg, 256>>>(W);
    k_stats<<<768, 256>>>();
    k_pass_s<1><<<pg, 256>>>(W);
    k_finalize_v<<<200, 256>>>(out_len);

    k_pass_agree<1><<<pg, 256>>>(W);
    k_stats<<<768, 256>>>();
    k_pass_s<1><<<pg, 256>>>(W);
    k_finalize_v<<<200, 256>>>(out_len);

    k_mlp1<<<64, 512>>>(w1, b1, out_len);
    k_mlp2<<<64, 256>>>(w2, b2);
    k_mlp3<<<dim3(149, 2), 256>>>(w3);
    k_mlp3fin<<<1188, 256>>>(b3, out_recon);
}

// round 16
// speedup vs baseline: 2.2288x; 2.2288x over previous
#include <cuda_runtime.h>
#include <math.h>

#define BATCH 64
#define SEQ   200
#define EMBED 64
#define NCAPS 50
#define R_TOT 3072
#define LOUT  96
#define RT    32
#define NRB   96
#define WS    132
#define US    516
#define NPAD  19008

typedef unsigned long long ull_t;

__device__ __align__(16) float g_cwt[576 * 256];
__device__ __align__(16) float g_u[(size_t)BATCH * R_TOT * 8];
__device__ __align__(16) float g_blog[(size_t)NCAPS * R_TOT * BATCH];
__device__ __align__(16) float g_coeff[(size_t)NCAPS * R_TOT * BATCH];
__device__ __align__(16) float g_spart[(size_t)NCAPS * NRB * BATCH * 16];
__device__ __align__(16) float g_v[BATCH * NCAPS * 16];
__device__ __align__(16) float g_h1[BATCH * 512];
__device__ __align__(16) float g_h2[BATCH * 1024];
__device__ __align__(16) float g_r3p[2 * BATCH * NPAD];

__device__ __forceinline__ ull_t pk2(float a, float b) {
    ull_t r;
    asm("mov.b64 %0, {%1, %2};" : "=l"(r) : "f"(a), "f"(b));
    return r;
}
__device__ __forceinline__ void fma2(ull_t& d, ull_t a, ull_t b) {
    asm("fma.rn.f32x2 %0, %1, %2, %0;" : "+l"(d) : "l"(a), "l"(b));
}
__device__ __forceinline__ ull_t add2(ull_t a, ull_t b) {
    ull_t r;
    asm("add.rn.f32x2 %0, %1, %2;" : "=l"(r) : "l"(a), "l"(b));
    return r;
}
__device__ __forceinline__ float2 upk(ull_t v) {
    float2 f;
    asm("mov.b64 {%0, %1}, %2;" : "=f"(f.x), "=f"(f.y) : "l"(v));
    return f;
}
__device__ __forceinline__ void cpa16(void* s, const void* g) {
    unsigned sa = (unsigned)__cvta_generic_to_shared(s);
    asm volatile("cp.async.ca.shared.global [%0], [%1], 16;" :: "r"(sa), "l"(g));
}
#define CP_COMMIT asm volatile("cp.async.commit_group;")
#define CP_WAIT0  asm volatile("cp.async.wait_group 0;" ::: "memory")

__device__ __forceinline__ void stage_W(const float* __restrict__ W, int c, int r0,
                                        int tid, float* dst) {
#pragma unroll
    for (int k = 0; k < 4; k++) {
        int idx = tid + k * 256;
        int rl = idx >> 5, q = idx & 31;
        cpa16(dst + rl * WS + q * 4, W + ((size_t)c * R_TOT + r0 + rl) * 128 + q * 4);
    }
}
__device__ __forceinline__ void stage_u(int r0, int tid, float* dst) {
#pragma unroll
    for (int k = 0; k < 16; k++) {
        int idx = tid + k * 256;
        int b = idx >> 6, t = idx & 63;
        int rl = t >> 1, i4 = (t & 1) * 4;
        cpa16(dst + rl * US + b * 8 + i4, g_u + ((size_t)b * R_TOT + r0 + rl) * 8 + i4);
    }
}

__global__ void k_transpose_w(const float* __restrict__ conv_w) {
    g_cwt[blockIdx.x * 256 + threadIdx.x] = conv_w[threadIdx.x * 576 + blockIdx.x];
}

__global__ void k_conv(const int* __restrict__ x, const float* __restrict__ emb,
                       const float* __restrict__ conv_b) {
    int b = blockIdx.x, l0 = blockIdx.y * 16, tid = threadIdx.x;
    __shared__ float xs[39 * 64];
    for (int idx = tid; idx < 39 * 16; idx += 256) {
        int row = idx >> 4, col = idx & 15;
        int tok = x[b * SEQ + 2 * l0 + row];
        ((float4*)xs)[row * 16 + col] = ((const float4*)(emb + (size_t)tok * EMBED))[col];
    }
    __syncthreads();
    int ch = tid;
    float acc[16], bias = conv_b[ch];
#pragma unroll
    for (int j = 0; j < 16; j++) acc[j] = bias;
    for (int e = 0; e < 64; e++) {
#pragma unroll
        for (int k = 0; k < 9; k++) {
            float w = g_cwt[(e * 9 + k) * 256 + ch];
#pragma unroll
            for (int j = 0; j < 16; j++)
                acc[j] = fmaf(xs[(2 * j + k) * 64 + e], w, acc[j]);
        }
    }
    int g = ch >> 3, i = ch & 7;
#pragma unroll
    for (int j = 0; j < 16; j++) {
        float val = acc[j] > 0.f ? acc[j] : 0.f;
        g_u[((size_t)b * R_TOT + g * LOUT + l0 + j) * 8 + i] = val;
    }
}

// ---------------- pass_s: 2 capsules per block, u staged once ---------------
// thread: rg = tid&7 (4 routes rl = rr*8+rg), bg = tid>>3 (2 batches b0=bg*2)
template <int MODE>   // 0 = uniform 1/50, 1 = g_coeff
__global__ void __launch_bounds__(256, 2) k_pass_s(const float* __restrict__ W) {
    __shared__ float u_sh[RT * US];
    __shared__ float Ws[2][RT * WS];
    int rb = blockIdx.x, c0 = blockIdx.y * 2;
    int r0 = rb * RT, tid = threadIdx.x;
    int rg = tid & 7, bg = tid >> 3, b0 = bg * 2;

    stage_u(r0, tid, u_sh);
    stage_W(W, c0, r0, tid, Ws[0]);
    CP_COMMIT; CP_WAIT0; __syncthreads();

#pragma unroll
    for (int cc = 0; cc < 2; cc++) {
        int c = c0 + cc;
        if (cc == 0) { stage_W(W, c0 + 1, r0, tid, Ws[1]); CP_COMMIT; }

        float2 cfr[4];
        if (MODE == 1) {
#pragma unroll
            for (int rr = 0; rr < 4; rr++)
                cfr[rr] = *(const float2*)(g_coeff +
                    ((size_t)c * R_TOT + r0 + rr * 8 + rg) * 64 + b0);
        }

        ull_t acc0[8], acc1[8];
#pragma unroll
        for (int k = 0; k < 8; k++) { acc0[k] = 0ull; acc1[k] = 0ull; }

#pragma unroll
        for (int rr = 0; rr < 4; rr++) {
            int rl = rr * 8 + rg;
            float cf0, cf1;
            if (MODE == 0) { cf0 = cf1 = 0.02f; }
            else { cf0 = cfr[rr].x; cf1 = cfr[rr].y; }
            const float* up = &u_sh[rl * US + b0 * 8];
            float4 a0 = *(const float4*)(up);
            float4 a1 = *(const float4*)(up + 4);
            float4 d0 = *(const float4*)(up + 8);
            float4 d1 = *(const float4*)(up + 12);
            float su0[8] = {cf0*a0.x, cf0*a0.y, cf0*a0.z, cf0*a0.w,
                            cf0*a1.x, cf0*a1.y, cf0*a1.z, cf0*a1.w};
            float su1[8] = {cf1*d0.x, cf1*d0.y, cf1*d0.z, cf1*d0.w,
                            cf1*d1.x, cf1*d1.y, cf1*d1.z, cf1*d1.w};
            const float* wrow = &Ws[cc][rl * WS];
#pragma unroll
            for (int i = 0; i < 8; i++) {
                ull_t s0 = pk2(su0[i], su0[i]);
                ull_t s1 = pk2(su1[i], su1[i]);
#pragma unroll
                for (int o4 = 0; o4 < 4; o4++) {
                    ulonglong2 wp = *(const ulonglong2*)&wrow[i * 16 + o4 * 4];
                    fma2(acc0[o4 * 2 + 0], s0, wp.x);
                    fma2(acc0[o4 * 2 + 1], s0, wp.y);
                    fma2(acc1[o4 * 2 + 0], s1, wp.x);
                    fma2(acc1[o4 * 2 + 1], s1, wp.y);
                }
            }
        }
#pragma unroll
        for (int m = 1; m <= 4; m <<= 1)
#pragma unroll
            for (int k = 0; k < 8; k++) {
                acc0[k] = add2(acc0[k], __shfl_xor_sync(0xffffffffu, acc0[k], m));
                acc1[k] = add2(acc1[k], __shfl_xor_sync(0xffffffffu, acc1[k], m));
            }
        if (rg == 0) {
            ull_t* dst = (ull_t*)(g_spart + (((size_t)c * NRB + rb) * BATCH + b0) * 16);
#pragma unroll
            for (int k = 0; k < 8; k++) dst[k] = acc0[k];
#pragma unroll
            for (int k = 0; k < 8; k++) dst[8 + k] = acc1[k];
        }
        if (cc == 0) { CP_WAIT0; __syncthreads(); }
    }
}

// ---------------- pass_agree: 2 capsules per block ---------------------------
template <int ACC>
__global__ void __launch_bounds__(256, 2) k_pass_agree(const float* __restrict__ W) {
    __shared__ float u_sh[RT * US];
    __shared__ float Ws[2][RT * WS];
    int rb = blockIdx.x, c0 = blockIdx.y * 2;
    int r0 = rb * RT, tid = threadIdx.x;
    int rg = tid & 7, bg = tid >> 3, b0 = bg * 2;

    stage_u(r0, tid, u_sh);
    stage_W(W, c0, r0, tid, Ws[0]);
    CP_COMMIT; CP_WAIT0; __syncthreads();

#pragma unroll
    for (int cc = 0; cc < 2; cc++) {
        int c = c0 + cc;
        if (cc == 0) { stage_W(W, c0 + 1, r0, tid, Ws[1]); CP_COMMIT; }

        ull_t vp0[8], vp1[8];
        {
            const ulonglong2* v0 = (const ulonglong2*)(g_v + ((size_t)b0 * NCAPS + c) * 16);
            const ulonglong2* v1 = (const ulonglong2*)(g_v + ((size_t)(b0 + 1) * NCAPS + c) * 16);
#pragma unroll
            for (int q = 0; q < 4; q++) {
                ulonglong2 t0 = v0[q], t1 = v1[q];
                vp0[q * 2] = t0.x; vp0[q * 2 + 1] = t0.y;
                vp1[q * 2] = t1.x; vp1[q * 2 + 1] = t1.y;
            }
        }
#pragma unroll
        for (int rr = 0; rr < 4; rr++) {
            int rl = rr * 8 + rg;
            int r = r0 + rl;
            const float* wrow = &Ws[cc][rl * WS];
            float gg0[8], gg1[8];
#pragma unroll
            for (int i = 0; i < 8; i++) {
                ull_t gi0 = 0ull, gi1 = 0ull;
#pragma unroll
                for (int o4 = 0; o4 < 4; o4++) {
                    ulonglong2 wp = *(const ulonglong2*)&wrow[i * 16 + o4 * 4];
                    fma2(gi0, wp.x, vp0[o4 * 2]); fma2(gi0, wp.y, vp0[o4 * 2 + 1]);
                    fma2(gi1, wp.x, vp1[o4 * 2]); fma2(gi1, wp.y, vp1[o4 * 2 + 1]);
                }
                float2 t0 = upk(gi0), t1 = upk(gi1);
                gg0[i] = t0.x + t0.y;
                gg1[i] = t1.x + t1.y;
            }
            const float* up = &u_sh[rl * US + b0 * 8];
            float4 a0 = *(const float4*)(up);
            float4 a1 = *(const float4*)(up + 4);
            float4 d0 = *(const float4*)(up + 8);
            float4 d1 = *(const float4*)(up + 12);
            float add0 = a0.x*gg0[0] + a0.y*gg0[1] + a0.z*gg0[2] + a0.w*gg0[3]
                       + a1.x*gg0[4] + a1.y*gg0[5] + a1.z*gg0[6] + a1.w*gg0[7];
            float add1 = d0.x*gg1[0] + d0.y*gg1[1] + d0.z*gg1[2] + d0.w*gg1[3]
                       + d1.x*gg1[4] + d1.y*gg1[5] + d1.z*gg1[6] + d1.w*gg1[7];
            float* dst = g_blog + ((size_t)c * R_TOT + r) * 64 + b0;
            float2 res = make_float2(add0, add1);
            if (ACC) {
                float2 old = *(const float2*)dst;
                res.x += old.x; res.y += old.y;
            }
            *(float2*)dst = res;
        }
        if (cc == 0) { CP_WAIT0; __syncthreads(); }
    }
}

__global__ void k_coeff() {
    int idx = blockIdx.x * 256 + threadIdx.x;   // r*64+b
    float e[NCAPS];
    float mx = -1e30f;
#pragma unroll
    for (int c = 0; c < NCAPS; c++) {
        e[c] = g_blog[(size_t)c * (R_TOT * 64) + idx];
        mx = fmaxf(mx, e[c]);
    }
    float sum = 0.f;
#pragma unroll
    for (int c = 0; c < NCAPS; c++) {
        e[c] = __expf(e[c] - mx);
        sum += e[c];
    }
    float iz = 1.f / sum;
#pragma unroll
    for (int c = 0; c < NCAPS; c++)
        g_coeff[(size_t)c * (R_TOT * 64) + idx] = e[c] * iz;
}

__global__ void k_finalize_v(float* __restrict__ out_len) {
    int gid = blockIdx.x * 256 + threadIdx.x;   // (b*50+c)*16+o, 51200
    int o = gid & 15;
    int bc = gid >> 4;
    int b = bc / NCAPS, c = bc % NCAPS;
    const float* base = g_spart + ((size_t)c * NRB * BATCH + b) * 16 + o;
    float s0 = 0.f, s1 = 0.f, s2 = 0.f, s3 = 0.f;
#pragma unroll 6
    for (int rb = 0; rb < NRB; rb += 4) {
        s0 += base[(size_t)(rb + 0) * BATCH * 16];
        s1 += base[(size_t)(rb + 1) * BATCH * 16];
        s2 += base[(size_t)(rb + 2) * BATCH * 16];
        s3 += base[(size_t)(rb + 3) * BATCH * 16];
    }
    float s = (s0 + s1) + (s2 + s3);
    float nsq = s * s;
#pragma unroll
    for (int m = 1; m <= 8; m <<= 1)
        nsq += __shfl_xor_sync(0xffffffffu, nsq, m);
    float norm = sqrtf(nsq);
    float f = nsq / (1.f + nsq) / (norm + 1e-8f);
    g_v[gid] = f * s;
    if (o == 0) out_len[bc] = f * norm;
}

__global__ void k_mlp1(const float* __restrict__ w1, const float* __restrict__ b1,
                       const float* __restrict__ len) {
    int b = blockIdx.x;
    __shared__ float vv[16];
    __shared__ int cb_sh;
    if (threadIdx.x < 32) {
        float best = -1.f; int bi = 0;
        for (int c = threadIdx.x; c < NCAPS; c += 32) {
            float L = len[b * NCAPS + c];
            if (L > best || (L == best && c < bi)) { best = L; bi = c; }
        }
#pragma unroll
        for (int mm = 16; mm >= 1; mm >>= 1) {
            float ob = __shfl_xor_sync(0xffffffffu, best, mm);
            int oi = __shfl_xor_sync(0xffffffffu, bi, mm);
            if (ob > best || (ob == best && oi < bi)) { best = ob; bi = oi; }
        }
        if (threadIdx.x == 0) cb_sh = bi;
    }
    __syncthreads();
    int cb = cb_sh;
    if (threadIdx.x < 16)
        vv[threadIdx.x] = g_v[((size_t)b * NCAPS + cb) * 16 + threadIdx.x];
    __syncthreads();
    int n = threadIdx.x;
    float acc = b1[n];
#pragma unroll
    for (int o = 0; o < 16; o++)
        acc = fmaf(vv[o], w1[(size_t)(cb * 16 + o) * 512 + n], acc);
    g_h1[b * 512 + n] = acc > 0.f ? acc : 0.f;
}

__global__ void k_mlp2(const float* __restrict__ w2, const float* __restrict__ b2) {
    int b = blockIdx.x;
    __shared__ float hh[512];
    for (int i = threadIdx.x; i < 512; i += 256) hh[i] = g_h1[b * 512 + i];
    __syncthreads();
    int n0 = threadIdx.x * 4;
    float4 acc = *(const float4*)(b2 + n0);
    for (int k = 0; k < 512; k++) {
        float h = hh[k];
        float4 w = *(const float4*)(w2 + (size_t)k * 1024 + n0);
        acc.x = fmaf(h, w.x, acc.x); acc.y = fmaf(h, w.y, acc.y);
        acc.z = fmaf(h, w.z, acc.z); acc.w = fmaf(h, w.w, acc.w);
    }
    acc.x = fmaxf(acc.x, 0.f); acc.y = fmaxf(acc.y, 0.f);
    acc.z = fmaxf(acc.z, 0.f); acc.w = fmaxf(acc.w, 0.f);
    *(float4*)(g_h2 + (size_t)b * 1024 + n0) = acc;
}

// ---------------- mlp3: split-K x2, partials to g_r3p -----------------------
__global__ void k_mlp3(const float* __restrict__ w3) {
    int ncol0 = blockIdx.x * 128;
    int kh = blockIdx.y;
    __shared__ ull_t h2p[32 * 33];
    __shared__ float w3s[32 * 128];
    int tid = threadIdx.x;
    int bt = tid >> 5, ntid = tid & 31;
    int bp0 = bt * 4, n_off = ntid * 4;
    ull_t acc2[4][4];
#pragma unroll
    for (int jp = 0; jp < 4; jp++)
#pragma unroll
        for (int e = 0; e < 4; e++) acc2[jp][e] = 0ull;
    for (int kc = kh * 16; kc < kh * 16 + 16; kc++) {
        for (int idx = tid; idx < 32 * 32; idx += 256) {
            int bp = idx >> 5, kk = idx & 31;
            h2p[bp * 33 + kk] = pk2(g_h2[(size_t)(2 * bp) * 1024 + kc * 32 + kk],
                                    g_h2[(size_t)(2 * bp + 1) * 1024 + kc * 32 + kk]);
        }
        for (int idx = tid; idx < 32 * 32; idx += 256) {
            int kk = idx >> 5, jj = idx & 31;
            int col = ncol0 + jj * 4;
            float4 val;
            const float* row = w3 + (size_t)(kc * 32 + kk) * 19000;
            if (col + 3 < 19000) val = *(const float4*)(row + col);
            else {
                val.x = (col + 0 < 19000) ? row[col + 0] : 0.f;
                val.y = (col + 1 < 19000) ? row[col + 1] : 0.f;
                val.z = (col + 2 < 19000) ? row[col + 2] : 0.f;
                val.w = (col + 3 < 19000) ? row[col + 3] : 0.f;
            }
            *(float4*)&w3s[kk * 128 + jj * 4] = val;
        }
        __syncthreads();
        for (int kk = 0; kk < 32; kk++) {
            float4 w = *(const float4*)&w3s[kk * 128 + n_off];
            ull_t wp0 = pk2(w.x, w.x), wp1 = pk2(w.y, w.y);
            ull_t wp2 = pk2(w.z, w.z), wp3 = pk2(w.w, w.w);
#pragma unroll
            for (int jp = 0; jp < 4; jp++) {
                ull_t h = h2p[(bp0 + jp) * 33 + kk];
                fma2(acc2[jp][0], h, wp0); fma2(acc2[jp][1], h, wp1);
                fma2(acc2[jp][2], h, wp2); fma2(acc2[jp][3], h, wp3);
            }
        }
        __syncthreads();
    }
    float* part = g_r3p + (size_t)kh * BATCH * NPAD;
    int n = ncol0 + n_off;
#pragma unroll
    for (int jp = 0; jp < 4; jp++) {
        int b_even = (bp0 + jp) * 2;
#pragma unroll
        for (int e = 0; e < 4; e++) {
            int nn = n + e;
            if (nn < 19000) {
                float2 t = upk(acc2[jp][e]);
                part[(size_t)b_even * NPAD + nn] = t.x;
                part[(size_t)(b_even + 1) * NPAD + nn] = t.y;
            }
        }
    }
}

__global__ void k_mlp3fin(const float* __restrict__ b3, float* __restrict__ out_recon) {
    int gid = blockIdx.x * 256 + threadIdx.x;     // 64 * 4750 n4-tiles
    if (gid >= BATCH * 4750) return;
    int b = gid / 4750;
    int n = (gid - b * 4750) * 4;
    float4 p0 = *(const float4*)(g_r3p + (size_t)b * NPAD + n);
    float4 p1 = *(const float4*)(g_r3p + (size_t)(BATCH * NPAD) + (size_t)b * NPAD + n);
    float4 bb = *(const float4*)(b3 + n);
    float4 r;
    r.x = 1.f / (1.f + __expf(-(p0.x + p1.x + bb.x)));
    r.y = 1.f / (1.f + __expf(-(p0.y + p1.y + bb.y)));
    r.z = 1.f / (1.f + __expf(-(p0.z + p1.z + bb.z)));
    r.w = 1.f / (1.f + __expf(-(p0.w + p1.w + bb.w)));
    *(float4*)(out_recon + (size_t)b * 19000 + n) = r;
}

extern "C" void kernel_launch(void* const* d_in, const int* in_sizes, int n_in,
                              void* d_out, int out_size) {
    const int*   x      = (const int*)d_in[0];
    const float* emb    = (const float*)d_in[1];
    const float* conv_w = (const float*)d_in[2];
    const float* conv_b = (const float*)d_in[3];
    const float* W      = (const float*)d_in[4];
    const float* w1     = (const float*)d_in[5];
    const float* b1     = (const float*)d_in[6];
    const float* w2     = (const float*)d_in[7];
    const float* b2     = (const float*)d_in[8];
    const float* w3     = (const float*)d_in[9];
    const float* b3     = (const float*)d_in[10];
    float* out       = (float*)d_out;
    float* out_len   = out;
    float* out_recon = out + BATCH * NCAPS;

    dim3 pg(NRB, NCAPS / 2);   // 96 x 25, 2 capsules per block

    k_transpose_w<<<576, 256>>>(conv_w);
    k_conv<<<dim3(64, 6), 256>>>(x, emb, conv_b);

    k_pass_s<0><<<pg, 256>>>(W);
    k_finalize_v<<<200, 256>>>(out_len);

    k_pass_agree<0><<<pg, 256>>>(W);
    k_coeff<<<768, 256>>>();
    k_pass_s<1><<<pg, 256>>>(W);
    k_finalize_v<<<200, 256>>>(out_len);

    k_pass_agree<1><<<pg, 256>>>(W);
    k_coeff<<<768, 256>>>();
    k_pass_s<1><<<pg, 256>>>(W);
    k_finalize_v<<<200, 256>>>(out_len);

    k_mlp1<<<64, 512>>>(w1, b1, out_len);
    k_mlp2<<<64, 256>>>(w2, b2);
    k_mlp3<<<dim3(149, 2), 256>>>(w3);
    k_mlp3fin<<<1188, 256>>>(b3, out_recon);
}